// round 1
// baseline (speedup 1.0000x reference)
#include <cuda_runtime.h>
#include <math.h>

// ---------------- problem constants ----------------
#define BB      4
#define LL      2048
#define DMODEL  1024
#define DINNER  2048
#define DSTATE  16
#define DTRANK  64
#define NPROJ   (DTRANK + 2*DSTATE)   // 96
#define MTOT    (BB*LL)               // 8192

// ---------------- scratch (static device memory, no allocs) ----------------
__device__ float g_xz   [(size_t)MTOT * 2 * DINNER];   // 128 MB : [u | z]
__device__ float g_uc   [(size_t)MTOT * DINNER];       //  64 MB : conv+silu(u)
__device__ float g_proj [(size_t)MTOT * NPROJ];        //   3 MB : [dt_r | B | C]
__device__ float g_delta[(size_t)MTOT * DINNER];       //  64 MB : softplus(dt)
__device__ float g_y    [(size_t)MTOT * DINNER];       //  64 MB : scan out * silu(z)

// ---------------- generic fp32 tiled GEMM ----------------
// C[M,N] = A[M,K] @ B[K,N]   (row-major, lda/ldb/ldc strides)
// ACT==1: C = softplus(C + bias[n])
template<int BM, int BN, int BK, int TM, int TN, int ACT>
__global__ void sgemm_k(const float* __restrict__ A,
                        const float* __restrict__ Bm,
                        const float* __restrict__ bias,
                        float* __restrict__ C,
                        int M, int N, int K,
                        int lda, int ldb, int ldc)
{
    constexpr int THREADS = (BM/TM) * (BN/TN);
    __shared__ float As[BK][BM + 4];
    __shared__ float Bs[BK][BN + 4];

    const int tid = threadIdx.x;
    const int tx  = tid % (BN/TN);
    const int ty  = tid / (BN/TN);
    const int row0 = blockIdx.y * BM;
    const int col0 = blockIdx.x * BN;

    float acc[TM][TN];
#pragma unroll
    for (int m = 0; m < TM; m++)
#pragma unroll
        for (int n = 0; n < TN; n++) acc[m][n] = 0.f;

    for (int k0 = 0; k0 < K; k0 += BK) {
        // load A tile (BM x BK), store transposed: As[k][m]
#pragma unroll 2
        for (int i = tid; i < BM*BK; i += THREADS) {
            int m = i / BK, k = i % BK;
            As[k][m] = A[(size_t)(row0 + m) * lda + (k0 + k)];
        }
        // load B tile (BK x BN)
#pragma unroll 2
        for (int i = tid; i < BK*BN; i += THREADS) {
            int k = i / BN, n = i % BN;
            Bs[k][n] = Bm[(size_t)(k0 + k) * ldb + (col0 + n)];
        }
        __syncthreads();

#pragma unroll
        for (int kk = 0; kk < BK; kk++) {
            float a[TM], b[TN];
#pragma unroll
            for (int m = 0; m < TM; m++) a[m] = As[kk][ty*TM + m];
#pragma unroll
            for (int n = 0; n < TN; n++) b[n] = Bs[kk][tx*TN + n];
#pragma unroll
            for (int m = 0; m < TM; m++)
#pragma unroll
                for (int n = 0; n < TN; n++)
                    acc[m][n] = fmaf(a[m], b[n], acc[m][n]);
        }
        __syncthreads();
    }

#pragma unroll
    for (int m = 0; m < TM; m++) {
        int gm = row0 + ty*TM + m;
#pragma unroll
        for (int n = 0; n < TN; n++) {
            int gn = col0 + tx*TN + n;
            float v = acc[m][n];
            if (ACT == 1) {
                v += bias[gn];
                // softplus, numerically safe
                v = (v > 20.f) ? v : log1pf(__expf(v));
            }
            C[(size_t)gm * ldc + gn] = v;
        }
    }
}

// ---------------- causal depthwise conv (4 taps) + bias + silu ----------------
// input: u = g_xz[:, 0:DINNER] (stride 2*DINNER per row), output: g_uc
__global__ void conv_silu_k(const float* __restrict__ conv_w,
                            const float* __restrict__ conv_b)
{
    int idx = blockIdx.x * blockDim.x + threadIdx.x;
    if (idx >= MTOT * DINNER) return;
    int d = idx % DINNER;
    int r = idx / DINNER;          // b*L + t
    int t = r % LL;

    const float4 w = ((const float4*)conv_w)[d];   // taps w0..w3
    const size_t stride = 2 * DINNER;
    const size_t col = (size_t)r * stride + d;

    float acc = conv_b[d];
    if (t >= 3) acc = fmaf(w.x, g_xz[col - 3*stride], acc);
    if (t >= 2) acc = fmaf(w.y, g_xz[col - 2*stride], acc);
    if (t >= 1) acc = fmaf(w.z, g_xz[col - 1*stride], acc);
    acc = fmaf(w.w, g_xz[col], acc);

    float s = acc / (1.f + __expf(-acc));          // silu
    g_uc[idx] = s;
}

// ---------------- selective scan ----------------
// one thread per (b,d) channel; 16 states in registers; sequential over t.
// fuses  + u*Dp  and  * silu(z)  into the epilogue, writes g_y (GEMM4 input).
__global__ void scan_k(const float* __restrict__ A_log,
                       const float* __restrict__ Dp)
{
    int ch = blockIdx.x * blockDim.x + threadIdx.x;   // 0..8191
    if (ch >= BB * DINNER) return;
    int b = ch / DINNER;
    int d = ch % DINNER;

    float Ac[DSTATE];
#pragma unroll
    for (int n = 0; n < DSTATE; n++)
        Ac[n] = -__expf(A_log[d*DSTATE + n]);
    const float Dpd = Dp[d];

    float h[DSTATE];
#pragma unroll
    for (int n = 0; n < DSTATE; n++) h[n] = 0.f;

    const int base = b * LL;
    for (int t = 0; t < LL; t++) {
        const int r = base + t;
        const float u  = g_uc   [(size_t)r*DINNER + d];
        const float dt = g_delta[(size_t)r*DINNER + d];
        const float* pr = g_proj + (size_t)r * NPROJ;
        const float du = dt * u;
        float y = 0.f;
#pragma unroll
        for (int n = 0; n < DSTATE; n++) {
            float dA = __expf(dt * Ac[n]);
            h[n] = fmaf(h[n], dA, du * __ldg(pr + DTRANK + n));
            y = fmaf(h[n], __ldg(pr + DTRANK + DSTATE + n), y);
        }
        y = fmaf(u, Dpd, y);
        const float z = g_xz[(size_t)r*(2*DINNER) + DINNER + d];
        const float sz = z / (1.f + __expf(-z));
        g_y[(size_t)r*DINNER + d] = y * sz;
    }
}

// ---------------- launch ----------------
extern "C" void kernel_launch(void* const* d_in, const int* in_sizes, int n_in,
                              void* d_out, int out_size)
{
    const float* x       = (const float*)d_in[0];
    const float* W_in    = (const float*)d_in[1];
    const float* conv_w  = (const float*)d_in[2];
    const float* conv_b  = (const float*)d_in[3];
    const float* W_xproj = (const float*)d_in[4];
    const float* W_dt    = (const float*)d_in[5];
    const float* b_dt    = (const float*)d_in[6];
    const float* A_log   = (const float*)d_in[7];
    const float* Dp      = (const float*)d_in[8];
    const float* W_out   = (const float*)d_in[9];
    float* out = (float*)d_out;

    float *xz, *uc, *proj, *delta, *ybuf;
    cudaGetSymbolAddress((void**)&xz,    g_xz);
    cudaGetSymbolAddress((void**)&uc,    g_uc);
    cudaGetSymbolAddress((void**)&proj,  g_proj);
    cudaGetSymbolAddress((void**)&delta, g_delta);
    cudaGetSymbolAddress((void**)&ybuf,  g_y);

    // 1) xz = x @ W_in           [8192,4096] K=1024
    sgemm_k<128,128,8,8,8,0><<<dim3(4096/128, MTOT/128), 256>>>(
        x, W_in, nullptr, xz, MTOT, 2*DINNER, DMODEL, DMODEL, 2*DINNER, 2*DINNER);

    // 2) u = silu(causal_conv(u) + b)
    conv_silu_k<<<(MTOT*DINNER + 255)/256, 256>>>(conv_w, conv_b);

    // 3) proj = uc @ W_xproj     [8192,96] K=2048
    sgemm_k<64,96,8,4,6,0><<<dim3(1, MTOT/64), 256>>>(
        uc, W_xproj, nullptr, proj, MTOT, NPROJ, DINNER, DINNER, NPROJ, NPROJ);

    // 4) delta = softplus(dt_r @ W_dt + b_dt)   [8192,2048] K=64 (dt_r strided in proj)
    sgemm_k<128,128,8,8,8,1><<<dim3(DINNER/128, MTOT/128), 256>>>(
        proj, W_dt, b_dt, delta, MTOT, DINNER, DTRANK, NPROJ, DINNER, DINNER);

    // 5) selective scan + (*silu(z)), writes g_y
    scan_k<<<(BB*DINNER)/32, 32>>>(A_log, Dp);

    // 6) out = y @ W_out         [8192,1024] K=2048
    sgemm_k<128,128,8,8,8,0><<<dim3(DMODEL/128, MTOT/128), 256>>>(
        ybuf, W_out, nullptr, out, MTOT, DMODEL, DINNER, DINNER, DMODEL, DMODEL);
}

// round 2
// speedup vs baseline: 1.7285x; 1.7285x over previous
#include <cuda_runtime.h>
#include <math.h>
#include <stdint.h>

// ---------------- problem constants ----------------
#define BB      4
#define LL      2048
#define DMODEL  1024
#define DINNER  2048
#define DSTATE  16
#define DTRANK  64
#define NPROJ   (DTRANK + 2*DSTATE)   // 96
#define MTOT    (BB*LL)               // 8192

// ---------------- scratch (static device memory, no allocs) ----------------
__device__ float g_xz   [(size_t)MTOT * 2 * DINNER];   // [u | z]
__device__ float g_uc   [(size_t)MTOT * DINNER];       // conv+silu(u)
__device__ float g_proj [(size_t)MTOT * NPROJ];        // [dt_r | B | C]
__device__ float g_delta[(size_t)MTOT * DINNER];       // softplus(dt)
__device__ float g_y    [(size_t)MTOT * DINNER];       // scan out * silu(z)

// ================= tf32 tensor-core GEMM =================
// C[M,N] = A[M,K] @ B[K,N], row-major with strides. Grid covers M,N exactly.
// ACT==1: C = softplus(C + bias[n])
#define TBM 128
#define TBN 128
#define TBK 32
#define ASTR 36     // As[m][k] row stride  (bank-perm: gg*4+tg distinct)
#define BSTR 136    // Bs[k][n] row stride  (bank-perm: tg*8+gg distinct)
#define ASZ (TBM*ASTR)
#define BSZ (TBK*BSTR)
#define GEMM_SMEM (2*(ASZ+BSZ)*4)   // 71680 B

__device__ __forceinline__ uint32_t f2tf(float x){
    uint32_t r; asm("cvt.rna.tf32.f32 %0, %1;" : "=r"(r) : "f"(x)); return r;
}
__device__ __forceinline__ void cpa16(void* s, const void* g){
    uint32_t sa = (uint32_t)__cvta_generic_to_shared(s);
    asm volatile("cp.async.cg.shared.global [%0], [%1], 16;" :: "r"(sa), "l"(g));
}

template<int ACT>
__global__ void __launch_bounds__(256)
tgemm_k(const float* __restrict__ A, const float* __restrict__ B,
        const float* __restrict__ bias, float* __restrict__ C,
        int K, int lda, int ldb, int ldc)
{
    extern __shared__ float sm[];
    float* Asb[2] = { sm, sm + ASZ };
    float* Bsb[2] = { sm + 2*ASZ, sm + 2*ASZ + BSZ };

    const int tid  = threadIdx.x;
    const int row0 = blockIdx.y * TBM;
    const int col0 = blockIdx.x * TBN;

    const int lane = tid & 31, wid = tid >> 5;
    const int gg = lane >> 2, tg = lane & 3;
    const int wm = (wid >> 2) * 64;    // warp row offset (0/64)
    const int wn = (wid & 3) * 32;     // warp col offset (0/32/64/96)

    // global load indices
    const int ar = tid >> 3, ac = (tid & 7) * 4;     // A: 32 rows/pass, 4 passes
    const int bk = tid >> 5, bc = (tid & 31) * 4;    // B: 8 rows/pass, 4 passes

    float acc[4][4][4];
#pragma unroll
    for (int i=0;i<4;i++)
#pragma unroll
    for (int j=0;j<4;j++)
#pragma unroll
    for (int k=0;k<4;k++) acc[i][j][k] = 0.f;

    const int NC = K / TBK;

    // prologue: load chunk 0 into buffer 0
    {
#pragma unroll
        for (int p=0;p<4;p++){
            int rr = ar + p*32;
            cpa16(&Asb[0][rr*ASTR + ac], A + (size_t)(row0+rr)*lda + ac);
        }
#pragma unroll
        for (int p=0;p<4;p++){
            int kk = bk + p*8;
            cpa16(&Bsb[0][kk*BSTR + bc], B + (size_t)kk*ldb + col0 + bc);
        }
        asm volatile("cp.async.commit_group;");
    }

    for (int kc = 0; kc < NC; kc++){
        if (kc + 1 < NC){
            const int k0 = (kc+1)*TBK;
            float* as = Asb[(kc+1)&1];
            float* bs = Bsb[(kc+1)&1];
#pragma unroll
            for (int p=0;p<4;p++){
                int rr = ar + p*32;
                cpa16(&as[rr*ASTR + ac], A + (size_t)(row0+rr)*lda + k0 + ac);
            }
#pragma unroll
            for (int p=0;p<4;p++){
                int kk = bk + p*8;
                cpa16(&bs[kk*BSTR + bc], B + (size_t)(k0+kk)*ldb + col0 + bc);
            }
            asm volatile("cp.async.commit_group;");
            asm volatile("cp.async.wait_group 1;");
        } else {
            asm volatile("cp.async.wait_group 0;");
        }
        __syncthreads();

        const float* as = Asb[kc&1];
        const float* bs = Bsb[kc&1];
#pragma unroll
        for (int ks = 0; ks < 4; ks++){
            const int kk = ks*8;
            uint32_t af[4][4], bf[4][2];
#pragma unroll
            for (int mt = 0; mt < 4; mt++){
                int r0 = (wm + mt*16 + gg)*ASTR + kk + tg;
                int r1 = r0 + 8*ASTR;
                af[mt][0] = f2tf(as[r0]);
                af[mt][1] = f2tf(as[r1]);
                af[mt][2] = f2tf(as[r0 + 4]);
                af[mt][3] = f2tf(as[r1 + 4]);
            }
#pragma unroll
            for (int nt = 0; nt < 4; nt++){
                int cb = wn + nt*8 + gg;
                bf[nt][0] = f2tf(bs[(kk+tg  )*BSTR + cb]);
                bf[nt][1] = f2tf(bs[(kk+tg+4)*BSTR + cb]);
            }
#pragma unroll
            for (int mt = 0; mt < 4; mt++)
#pragma unroll
                for (int nt = 0; nt < 4; nt++){
                    float* c = acc[mt][nt];
                    asm volatile(
                        "mma.sync.aligned.m16n8k8.row.col.f32.tf32.tf32.f32 "
                        "{%0,%1,%2,%3}, {%4,%5,%6,%7}, {%8,%9}, {%0,%1,%2,%3};"
                        : "+f"(c[0]), "+f"(c[1]), "+f"(c[2]), "+f"(c[3])
                        : "r"(af[mt][0]), "r"(af[mt][1]), "r"(af[mt][2]), "r"(af[mt][3]),
                          "r"(bf[nt][0]), "r"(bf[nt][1]));
                }
        }
        __syncthreads();
    }

    // epilogue
#pragma unroll
    for (int mt = 0; mt < 4; mt++){
#pragma unroll
        for (int nt = 0; nt < 4; nt++){
            int row = row0 + wm + mt*16 + gg;
            int col = col0 + wn + nt*8 + tg*2;
            float v0=acc[mt][nt][0], v1=acc[mt][nt][1],
                  v2=acc[mt][nt][2], v3=acc[mt][nt][3];
            if (ACT){
                float b0 = bias[col], b1 = bias[col+1];
                v0+=b0; v1+=b1; v2+=b0; v3+=b1;
                v0 = (v0>20.f)? v0 : log1pf(__expf(v0));
                v1 = (v1>20.f)? v1 : log1pf(__expf(v1));
                v2 = (v2>20.f)? v2 : log1pf(__expf(v2));
                v3 = (v3>20.f)? v3 : log1pf(__expf(v3));
            }
            *(float2*)&C[(size_t)row*ldc + col]     = make_float2(v0, v1);
            *(float2*)&C[(size_t)(row+8)*ldc + col] = make_float2(v2, v3);
        }
    }
}

// ================= fp32 tiled GEMM (for N=96 proj) =================
template<int BM, int BN, int BK, int TM, int TN>
__global__ void sgemm_k(const float* __restrict__ A,
                        const float* __restrict__ Bm,
                        float* __restrict__ C,
                        int K, int lda, int ldb, int ldc)
{
    constexpr int THREADS = (BM/TM) * (BN/TN);
    __shared__ float As[BK][BM + 4];
    __shared__ float Bs[BK][BN + 4];

    const int tid = threadIdx.x;
    const int tx  = tid % (BN/TN);
    const int ty  = tid / (BN/TN);
    const int row0 = blockIdx.y * BM;
    const int col0 = blockIdx.x * BN;

    float acc[TM][TN];
#pragma unroll
    for (int m = 0; m < TM; m++)
#pragma unroll
        for (int n = 0; n < TN; n++) acc[m][n] = 0.f;

    for (int k0 = 0; k0 < K; k0 += BK) {
#pragma unroll 2
        for (int i = tid; i < BM*BK; i += THREADS) {
            int m = i / BK, k = i % BK;
            As[k][m] = A[(size_t)(row0 + m) * lda + (k0 + k)];
        }
#pragma unroll 2
        for (int i = tid; i < BK*BN; i += THREADS) {
            int k = i / BN, n = i % BN;
            Bs[k][n] = Bm[(size_t)(k0 + k) * ldb + (col0 + n)];
        }
        __syncthreads();
#pragma unroll
        for (int kk = 0; kk < BK; kk++) {
            float a[TM], b[TN];
#pragma unroll
            for (int m = 0; m < TM; m++) a[m] = As[kk][ty*TM + m];
#pragma unroll
            for (int n = 0; n < TN; n++) b[n] = Bs[kk][tx*TN + n];
#pragma unroll
            for (int m = 0; m < TM; m++)
#pragma unroll
                for (int n = 0; n < TN; n++)
                    acc[m][n] = fmaf(a[m], b[n], acc[m][n]);
        }
        __syncthreads();
    }
#pragma unroll
    for (int m = 0; m < TM; m++) {
        int gm = row0 + ty*TM + m;
#pragma unroll
        for (int n = 0; n < TN; n++) {
            int gn = col0 + tx*TN + n;
            C[(size_t)gm * ldc + gn] = acc[m][n];
        }
    }
}

// ---------------- causal depthwise conv (4 taps) + bias + silu ----------------
__global__ void conv_silu_k(const float* __restrict__ conv_w,
                            const float* __restrict__ conv_b)
{
    int idx = blockIdx.x * blockDim.x + threadIdx.x;
    if (idx >= MTOT * DINNER) return;
    int d = idx % DINNER;
    int r = idx / DINNER;
    int t = r % LL;

    const float4 w = ((const float4*)conv_w)[d];
    const size_t stride = 2 * DINNER;
    const size_t col = (size_t)r * stride + d;

    float acc = conv_b[d];
    if (t >= 3) acc = fmaf(w.x, g_xz[col - 3*stride], acc);
    if (t >= 2) acc = fmaf(w.y, g_xz[col - 2*stride], acc);
    if (t >= 1) acc = fmaf(w.z, g_xz[col - 1*stride], acc);
    acc = fmaf(w.w, g_xz[col], acc);

    g_uc[idx] = acc / (1.f + __expf(-acc));
}

// ---------------- selective scan: 4 states per thread ----------------
// thread handles states [4q, 4q+4) of channel ch; y reduced via shfl_xor.
__global__ void scan_k(const float* __restrict__ A_log,
                       const float* __restrict__ Dp)
{
    int gt = blockIdx.x * blockDim.x + threadIdx.x;   // 0 .. 32767
    int ch = gt >> 2;
    int sq = gt & 3;
    int b = ch / DINNER;
    int d = ch % DINNER;
    int s0 = sq * 4;

    float Ac[4];
#pragma unroll
    for (int n = 0; n < 4; n++)
        Ac[n] = -__expf(A_log[d*DSTATE + s0 + n]);
    const float Dpd = Dp[d];

    float h[4] = {0.f, 0.f, 0.f, 0.f};
    const int base = b * LL;

    for (int t = 0; t < LL; t++) {
        const int r = base + t;
        const float u  = g_uc   [(size_t)r*DINNER + d];
        const float dt = g_delta[(size_t)r*DINNER + d];
        const float* pr = g_proj + (size_t)r * NPROJ;
        const float du = dt * u;
        float y = 0.f;
#pragma unroll
        for (int n = 0; n < 4; n++) {
            float dA = __expf(dt * Ac[n]);
            h[n] = fmaf(h[n], dA, du * __ldg(pr + DTRANK + s0 + n));
            y = fmaf(h[n], __ldg(pr + DTRANK + DSTATE + s0 + n), y);
        }
        y += __shfl_xor_sync(0xffffffffu, y, 1);
        y += __shfl_xor_sync(0xffffffffu, y, 2);
        if (sq == 0) {
            y = fmaf(u, Dpd, y);
            const float z = g_xz[(size_t)r*(2*DINNER) + DINNER + d];
            g_y[(size_t)r*DINNER + d] = y * (z / (1.f + __expf(-z)));
        }
    }
}

// ---------------- launch ----------------
extern "C" void kernel_launch(void* const* d_in, const int* in_sizes, int n_in,
                              void* d_out, int out_size)
{
    const float* x       = (const float*)d_in[0];
    const float* W_in    = (const float*)d_in[1];
    const float* conv_w  = (const float*)d_in[2];
    const float* conv_b  = (const float*)d_in[3];
    const float* W_xproj = (const float*)d_in[4];
    const float* W_dt    = (const float*)d_in[5];
    const float* b_dt    = (const float*)d_in[6];
    const float* A_log   = (const float*)d_in[7];
    const float* Dp      = (const float*)d_in[8];
    const float* W_out   = (const float*)d_in[9];
    float* out = (float*)d_out;

    float *xz, *uc, *proj, *delta, *ybuf;
    cudaGetSymbolAddress((void**)&xz,    g_xz);
    cudaGetSymbolAddress((void**)&uc,    g_uc);
    cudaGetSymbolAddress((void**)&proj,  g_proj);
    cudaGetSymbolAddress((void**)&delta, g_delta);
    cudaGetSymbolAddress((void**)&ybuf,  g_y);

    cudaFuncSetAttribute(tgemm_k<0>, cudaFuncAttributeMaxDynamicSharedMemorySize, GEMM_SMEM);
    cudaFuncSetAttribute(tgemm_k<1>, cudaFuncAttributeMaxDynamicSharedMemorySize, GEMM_SMEM);

    // 1) xz = x @ W_in   [8192,4096] K=1024  (tf32 TC)
    tgemm_k<0><<<dim3((2*DINNER)/TBN, MTOT/TBM), 256, GEMM_SMEM>>>(
        x, W_in, nullptr, xz, DMODEL, DMODEL, 2*DINNER, 2*DINNER);

    // 2) u = silu(causal_conv(u) + b)
    conv_silu_k<<<(MTOT*DINNER + 255)/256, 256>>>(conv_w, conv_b);

    // 3) proj = uc @ W_xproj   [8192,96] K=2048  (fp32)
    sgemm_k<64,96,8,4,6><<<dim3(1, MTOT/64), 256>>>(
        uc, W_xproj, proj, DINNER, DINNER, NPROJ, NPROJ);

    // 4) delta = softplus(dt_r @ W_dt + b_dt)  [8192,2048] K=64 (tf32 TC, strided A)
    tgemm_k<1><<<dim3(DINNER/TBN, MTOT/TBM), 256, GEMM_SMEM>>>(
        proj, W_dt, b_dt, delta, DTRANK, NPROJ, DINNER, DINNER);

    // 5) selective scan + *silu(z)
    scan_k<<<(4*BB*DINNER)/128, 128>>>(A_log, Dp);

    // 6) out = y @ W_out   [8192,1024] K=2048  (tf32 TC)
    tgemm_k<0><<<dim3(DMODEL/TBN, MTOT/TBM), 256, GEMM_SMEM>>>(
        ybuf, W_out, nullptr, out, DINNER, DINNER, DMODEL, DMODEL);
}

// round 5
// speedup vs baseline: 1.8332x; 1.0606x over previous
#include <cuda_runtime.h>
#include <math.h>
#include <stdint.h>

// ---------------- problem constants ----------------
#define BB      4
#define LL      2048
#define DMODEL  1024
#define DINNER  2048
#define DSTATE  16
#define DTRANK  64
#define NPROJ   (DTRANK + 2*DSTATE)   // 96
#define MTOT    (BB*LL)               // 8192

// ---------------- scratch (static device memory, no allocs) ----------------
__device__ float g_xz   [(size_t)MTOT * 2 * DINNER];
__device__ float g_uc   [(size_t)MTOT * DINNER];
__device__ float g_proj [(size_t)MTOT * NPROJ];
__device__ float g_delta[(size_t)MTOT * DINNER];
__device__ float g_y    [(size_t)MTOT * DINNER];
__device__ float g_xr   [(size_t)MTOT * DMODEL];        // tf32-rounded x
__device__ float g_wtin [(size_t)DMODEL * (2*DINNER)];  // rounded W_in  [1024,4096]
__device__ float g_wtout[(size_t)DINNER * DMODEL];      // rounded W_out [2048,1024]
__device__ float g_wdt  [(size_t)DTRANK * DINNER];      // rounded W_dt  [64,2048]

// ---------------- helpers ----------------
__device__ __forceinline__ uint32_t f2tf(float x){
    uint32_t r; asm("cvt.rna.tf32.f32 %0, %1;" : "=r"(r) : "f"(x)); return r;
}
__device__ __forceinline__ float roundtf(float x){ return __uint_as_float(f2tf(x)); }
__device__ __forceinline__ void cpa16(void* s, const void* g){
    uint32_t sa = (uint32_t)__cvta_generic_to_shared(s);
    asm volatile("cp.async.cg.shared.global [%0], [%1], 16;" :: "r"(sa), "l"(g));
}

// ================= mma.sync tf32 GEMM (inputs pre-rounded to tf32) =================
// C[M,N] = A[M,K] @ B[K,N], row-major + strides. ACT==1: softplus(C + bias[n]).
#define TBM 128
#define TBN 128
#define TBK 32
#define ASTR 36
#define BSTR 136
#define ASZ (TBM*ASTR)
#define BSZ (TBK*BSTR)
#define GEMM_SMEM (2*(ASZ+BSZ)*4)   // 71680 B

template<int ACT>
__global__ void __launch_bounds__(256, 2)
tgemm_k(const float* __restrict__ A, const float* __restrict__ B,
        const float* __restrict__ bias, float* __restrict__ C,
        int K, int lda, int ldb, int ldc)
{
    extern __shared__ float sm[];
    float* Asb[2] = { sm, sm + ASZ };
    float* Bsb[2] = { sm + 2*ASZ, sm + 2*ASZ + BSZ };

    const int tid  = threadIdx.x;
    const int row0 = blockIdx.y * TBM;
    const int col0 = blockIdx.x * TBN;
    const int lane = tid & 31, wid = tid >> 5;
    const int gg = lane >> 2, tg = lane & 3;
    const int wm = (wid >> 2) * 64;
    const int wn = (wid & 3) * 32;
    const int ar = tid >> 3, ac = (tid & 7) * 4;
    const int bk = tid >> 5, bc = (tid & 31) * 4;

    float acc[4][4][4];
#pragma unroll
    for (int i=0;i<4;i++)
#pragma unroll
    for (int j=0;j<4;j++)
#pragma unroll
    for (int k=0;k<4;k++) acc[i][j][k] = 0.f;

    const int NC = K / TBK;
    {
#pragma unroll
        for (int p=0;p<4;p++){
            int rr = ar + p*32;
            cpa16(&Asb[0][rr*ASTR + ac], A + (size_t)(row0+rr)*lda + ac);
        }
#pragma unroll
        for (int p=0;p<4;p++){
            int kk = bk + p*8;
            cpa16(&Bsb[0][kk*BSTR + bc], B + (size_t)kk*ldb + col0 + bc);
        }
        asm volatile("cp.async.commit_group;");
    }

    for (int kc = 0; kc < NC; kc++){
        if (kc + 1 < NC){
            const int k0 = (kc+1)*TBK;
            float* as = Asb[(kc+1)&1];
            float* bs = Bsb[(kc+1)&1];
#pragma unroll
            for (int p=0;p<4;p++){
                int rr = ar + p*32;
                cpa16(&as[rr*ASTR + ac], A + (size_t)(row0+rr)*lda + k0 + ac);
            }
#pragma unroll
            for (int p=0;p<4;p++){
                int kk = bk + p*8;
                cpa16(&bs[kk*BSTR + bc], B + (size_t)(k0+kk)*ldb + col0 + bc);
            }
            asm volatile("cp.async.commit_group;");
            asm volatile("cp.async.wait_group 1;");
        } else {
            asm volatile("cp.async.wait_group 0;");
        }
        __syncthreads();

        const float* as = Asb[kc&1];
        const float* bs = Bsb[kc&1];
#pragma unroll
        for (int ks = 0; ks < 4; ks++){
            const int kk = ks*8;
            float af[4][4], bf[4][2];
#pragma unroll
            for (int mt = 0; mt < 4; mt++){
                int r0 = (wm + mt*16 + gg)*ASTR + kk + tg;
                int r1 = r0 + 8*ASTR;
                af[mt][0] = as[r0];
                af[mt][1] = as[r1];
                af[mt][2] = as[r0 + 4];
                af[mt][3] = as[r1 + 4];
            }
#pragma unroll
            for (int nt = 0; nt < 4; nt++){
                int cb = wn + nt*8 + gg;
                bf[nt][0] = bs[(kk+tg  )*BSTR + cb];
                bf[nt][1] = bs[(kk+tg+4)*BSTR + cb];
            }
#pragma unroll
            for (int mt = 0; mt < 4; mt++)
#pragma unroll
                for (int nt = 0; nt < 4; nt++){
                    float* c = acc[mt][nt];
                    asm volatile(
                        "mma.sync.aligned.m16n8k8.row.col.f32.tf32.tf32.f32 "
                        "{%0,%1,%2,%3}, {%4,%5,%6,%7}, {%8,%9}, {%0,%1,%2,%3};"
                        : "+f"(c[0]), "+f"(c[1]), "+f"(c[2]), "+f"(c[3])
                        : "r"(__float_as_uint(af[mt][0])), "r"(__float_as_uint(af[mt][1])),
                          "r"(__float_as_uint(af[mt][2])), "r"(__float_as_uint(af[mt][3])),
                          "r"(__float_as_uint(bf[nt][0])), "r"(__float_as_uint(bf[nt][1])));
                }
        }
        __syncthreads();
    }

#pragma unroll
    for (int mt = 0; mt < 4; mt++){
#pragma unroll
        for (int nt = 0; nt < 4; nt++){
            int row = row0 + wm + mt*16 + gg;
            int col = col0 + wn + nt*8 + tg*2;
            float v0=acc[mt][nt][0], v1=acc[mt][nt][1],
                  v2=acc[mt][nt][2], v3=acc[mt][nt][3];
            if (ACT){
                float b0 = bias[col], b1 = bias[col+1];
                v0+=b0; v1+=b1; v2+=b0; v3+=b1;
                v0 = (v0>20.f)? v0 : log1pf(__expf(v0));
                v1 = (v1>20.f)? v1 : log1pf(__expf(v1));
                v2 = (v2>20.f)? v2 : log1pf(__expf(v2));
                v3 = (v3>20.f)? v3 : log1pf(__expf(v3));
            }
            *(float2*)&C[(size_t)row*ldc + col]     = make_float2(v0, v1);
            *(float2*)&C[(size_t)(row+8)*ldc + col] = make_float2(v2, v3);
        }
    }
}

// ================= round-copy prepass =================
__global__ void round_copy_k(const float4* __restrict__ src, float4* __restrict__ dst, int n4){
    int i = blockIdx.x * blockDim.x + threadIdx.x;
    if (i >= n4) return;
    float4 v = src[i];
    dst[i] = make_float4(roundtf(v.x), roundtf(v.y), roundtf(v.z), roundtf(v.w));
}

// ================= fp32 tiled GEMM (proj, N=96) =================
// epilogue: dt_r columns (gn < DTRANK) rounded to tf32 for the delta GEMM.
template<int BM, int BN, int BK, int TM, int TN>
__global__ void sgemm_k(const float* __restrict__ A,
                        const float* __restrict__ Bm,
                        float* __restrict__ C,
                        int K, int lda, int ldb, int ldc)
{
    constexpr int THREADS = (BM/TM) * (BN/TN);
    __shared__ float As[BK][BM + 4];
    __shared__ float Bs[BK][BN + 4];

    const int tid = threadIdx.x;
    const int tx  = tid % (BN/TN);
    const int ty  = tid / (BN/TN);
    const int row0 = blockIdx.y * BM;
    const int col0 = blockIdx.x * BN;

    float acc[TM][TN];
#pragma unroll
    for (int m = 0; m < TM; m++)
#pragma unroll
        for (int n = 0; n < TN; n++) acc[m][n] = 0.f;

    for (int k0 = 0; k0 < K; k0 += BK) {
#pragma unroll 2
        for (int i = tid; i < BM*BK; i += THREADS) {
            int m = i / BK, k = i % BK;
            As[k][m] = A[(size_t)(row0 + m) * lda + (k0 + k)];
        }
#pragma unroll 2
        for (int i = tid; i < BK*BN; i += THREADS) {
            int k = i / BN, n = i % BN;
            Bs[k][n] = Bm[(size_t)(k0 + k) * ldb + (col0 + n)];
        }
        __syncthreads();
#pragma unroll
        for (int kk = 0; kk < BK; kk++) {
            float a[TM], b[TN];
#pragma unroll
            for (int m = 0; m < TM; m++) a[m] = As[kk][ty*TM + m];
#pragma unroll
            for (int n = 0; n < TN; n++) b[n] = Bs[kk][tx*TN + n];
#pragma unroll
            for (int m = 0; m < TM; m++)
#pragma unroll
                for (int n = 0; n < TN; n++)
                    acc[m][n] = fmaf(a[m], b[n], acc[m][n]);
        }
        __syncthreads();
    }
#pragma unroll
    for (int m = 0; m < TM; m++) {
        int gm = row0 + ty*TM + m;
#pragma unroll
        for (int n = 0; n < TN; n++) {
            int gn = col0 + tx*TN + n;
            float v = acc[m][n];
            if (gn < DTRANK) v = roundtf(v);   // dt_r feeds tf32 delta GEMM
            C[(size_t)gm * ldc + gn] = v;
        }
    }
}

// ---------------- causal depthwise conv + bias + silu ----------------
__global__ void conv_silu_k(const float* __restrict__ conv_w,
                            const float* __restrict__ conv_b)
{
    int idx = blockIdx.x * blockDim.x + threadIdx.x;
    if (idx >= MTOT * DINNER) return;
    int d = idx % DINNER;
    int r = idx / DINNER;
    int t = r % LL;

    const float4 w = ((const float4*)conv_w)[d];
    const size_t stride = 2 * DINNER;
    const size_t col = (size_t)r * stride + d;

    float acc = conv_b[d];
    if (t >= 3) acc = fmaf(w.x, g_xz[col - 3*stride], acc);
    if (t >= 2) acc = fmaf(w.y, g_xz[col - 2*stride], acc);
    if (t >= 1) acc = fmaf(w.z, g_xz[col - 1*stride], acc);
    acc = fmaf(w.w, g_xz[col], acc);

    g_uc[idx] = acc / (1.f + __expf(-acc));
}

// ---------------- selective scan: 4 states per thread ----------------
__global__ void scan_k(const float* __restrict__ A_log,
                       const float* __restrict__ Dp)
{
    int gt = blockIdx.x * blockDim.x + threadIdx.x;
    int ch = gt >> 2;
    int sq = gt & 3;
    int b = ch / DINNER;
    int d = ch % DINNER;
    int s0 = sq * 4;

    float Ac[4];
#pragma unroll
    for (int n = 0; n < 4; n++)
        Ac[n] = -__expf(A_log[d*DSTATE + s0 + n]);
    const float Dpd = Dp[d];

    float h[4] = {0.f, 0.f, 0.f, 0.f};
    const int base = b * LL;

    for (int t = 0; t < LL; t++) {
        const int r = base + t;
        const float u  = g_uc   [(size_t)r*DINNER + d];
        const float dt = g_delta[(size_t)r*DINNER + d];
        const float* pr = g_proj + (size_t)r * NPROJ;
        const float du = dt * u;
        float y = 0.f;
#pragma unroll
        for (int n = 0; n < 4; n++) {
            float dA = __expf(dt * Ac[n]);
            h[n] = fmaf(h[n], dA, du * __ldg(pr + DTRANK + s0 + n));
            y = fmaf(h[n], __ldg(pr + DTRANK + DSTATE + s0 + n), y);
        }
        y += __shfl_xor_sync(0xffffffffu, y, 1);
        y += __shfl_xor_sync(0xffffffffu, y, 2);
        if (sq == 0) {
            y = fmaf(u, Dpd, y);
            const float z = g_xz[(size_t)r*(2*DINNER) + DINNER + d];
            g_y[(size_t)r*DINNER + d] = roundtf(y * (z / (1.f + __expf(-z))));
        }
    }
}

// ---------------- launch ----------------
extern "C" void kernel_launch(void* const* d_in, const int* in_sizes, int n_in,
                              void* d_out, int out_size)
{
    const float* x       = (const float*)d_in[0];
    const float* W_in    = (const float*)d_in[1];
    const float* conv_w  = (const float*)d_in[2];
    const float* conv_b  = (const float*)d_in[3];
    const float* W_xproj = (const float*)d_in[4];
    const float* W_dt    = (const float*)d_in[5];
    const float* b_dt    = (const float*)d_in[6];
    const float* A_log   = (const float*)d_in[7];
    const float* Dp      = (const float*)d_in[8];
    const float* W_out   = (const float*)d_in[9];
    float* out = (float*)d_out;

    float *xz, *uc, *proj, *delta, *ybuf, *xr, *wtin, *wtout, *wdt;
    cudaGetSymbolAddress((void**)&xz,    g_xz);
    cudaGetSymbolAddress((void**)&uc,    g_uc);
    cudaGetSymbolAddress((void**)&proj,  g_proj);
    cudaGetSymbolAddress((void**)&delta, g_delta);
    cudaGetSymbolAddress((void**)&ybuf,  g_y);
    cudaGetSymbolAddress((void**)&xr,    g_xr);
    cudaGetSymbolAddress((void**)&wtin,  g_wtin);
    cudaGetSymbolAddress((void**)&wtout, g_wtout);
    cudaGetSymbolAddress((void**)&wdt,   g_wdt);

    cudaFuncSetAttribute(tgemm_k<0>, cudaFuncAttributeMaxDynamicSharedMemorySize, GEMM_SMEM);
    cudaFuncSetAttribute(tgemm_k<1>, cudaFuncAttributeMaxDynamicSharedMemorySize, GEMM_SMEM);

    // 0) tf32 pre-rounding (removes cvt from GEMM mainloops)
    round_copy_k<<<(MTOT*DMODEL/4 + 255)/256, 256>>>((const float4*)x, (float4*)xr, MTOT*DMODEL/4);
    round_copy_k<<<(DMODEL*2*DINNER/4 + 255)/256, 256>>>((const float4*)W_in, (float4*)wtin, DMODEL*2*DINNER/4);
    round_copy_k<<<(DINNER*DMODEL/4 + 255)/256, 256>>>((const float4*)W_out, (float4*)wtout, DINNER*DMODEL/4);
    round_copy_k<<<(DTRANK*DINNER/4 + 255)/256, 256>>>((const float4*)W_dt, (float4*)wdt, DTRANK*DINNER/4);

    // 1) xz = x @ W_in   [8192,4096] K=1024
    tgemm_k<0><<<dim3((2*DINNER)/TBN, MTOT/TBM), 256, GEMM_SMEM>>>(
        xr, wtin, nullptr, xz, DMODEL, DMODEL, 2*DINNER, 2*DINNER);

    // 2) u = silu(causal_conv(u) + b)
    conv_silu_k<<<(MTOT*DINNER + 255)/256, 256>>>(conv_w, conv_b);

    // 3) proj = uc @ W_xproj   [8192,96] K=2048 (fp32; dt_r cols rounded)
    sgemm_k<32,96,16,2,6><<<dim3(1, MTOT/32), 256>>>(
        uc, W_xproj, proj, DINNER, DINNER, NPROJ, NPROJ);

    // 4) delta = softplus(dt_r @ W_dt + b_dt)  [8192,2048] K=64
    tgemm_k<1><<<dim3(DINNER/TBN, MTOT/TBM), 256, GEMM_SMEM>>>(
        proj, wdt, b_dt, delta, DTRANK, NPROJ, DINNER, DINNER);

    // 5) selective scan + *silu(z)  (writes tf32-rounded y)
    scan_k<<<(4*BB*DINNER)/128, 128>>>(A_log, Dp);

    // 6) out = y @ W_out   [8192,1024] K=2048
    tgemm_k<0><<<dim3(DMODEL/TBN, MTOT/TBM), 256, GEMM_SMEM>>>(
        ybuf, wtout, nullptr, out, DINNER, DINNER, DMODEL, DMODEL);
}